// round 15
// baseline (speedup 1.0000x reference)
#include <cuda_runtime.h>
#include <cuda_fp16.h>
#include <cstdint>
#include <math.h>

#define NL 8
#define NE 8
#define ND 256
#define NB 16384
#define TM 64
#define NTH 256

// ---------------- helpers ----------------
__device__ __forceinline__ uint32_t h2pk(float a, float b) {
    __half2 h = __floats2half2_rn(a, b);
    return *(uint32_t*)&h;
}
// exact split: a = hi + lo (both fp16), packed pairwise
__device__ __forceinline__ void split2(float a, float b, uint32_t& hi, uint32_t& lo) {
    __half ha = __float2half_rn(a), hb = __float2half_rn(b);
    __half2 hh = __halves2half2(ha, hb);
    hi = *(uint32_t*)&hh;
    lo = h2pk(a - __half2float(ha), b - __half2float(hb));
}

#define MMA16(c, A, b0, b1) \
    asm volatile("mma.sync.aligned.m16n8k16.row.col.f32.f16.f16.f32 " \
        "{%0,%1,%2,%3},{%4,%5,%6,%7},{%8,%9},{%0,%1,%2,%3};" \
        : "+f"((c)[0]), "+f"((c)[1]), "+f"((c)[2]), "+f"((c)[3]) \
        : "r"((A).x), "r"((A).y), "r"((A).z), "r"((A).w), "r"(b0), "r"(b1))

#define MMA8(c, a0, a1, b0) \
    asm volatile("mma.sync.aligned.m16n8k8.row.col.f32.f16.f16.f32 " \
        "{%0,%1,%2,%3},{%4,%5},{%6},{%0,%1,%2,%3};" \
        : "+f"((c)[0]), "+f"((c)[1]), "+f"((c)[2]), "+f"((c)[3]) \
        : "r"(a0), "r"(a1), "r"(b0))

// ---------------- global weight images (fp16 B-fragments) ----------------
// per (l,e): W1 32768 (kb-major contiguous) | W2 4096 | W3 16384
#define PER_LE 53248
#define B3OFF (64 * PER_LE)
__device__ __align__(16) unsigned char g_w[B3OFF + 8 * 4096];

__global__ void prep_kernel(const float* __restrict__ W1, const float* __restrict__ W2,
                            const float* __restrict__ W3, const float* __restrict__ b3) {
    const int le = blockIdx.x;
    const int t = threadIdx.x;
    unsigned char* base = g_w + (size_t)le * PER_LE;

    const float* W1p = W1 + (size_t)le * 16384;   // [64][256]
    for (int idx = t; idx < 4096; idx += 256) {   // (kb 0..15, nt 0..7, ln)
        int kb = idx >> 8, nt = (idx >> 5) & 7, ln = idx & 31;
        int g = ln >> 2, tig = ln & 3;
        int n = nt * 8 + g, k = kb * 16 + 2 * tig;
        *(uint2*)(base + idx * 8) = make_uint2(
            h2pk(W1p[n * 256 + k], W1p[n * 256 + k + 1]),
            h2pk(W1p[n * 256 + k + 8], W1p[n * 256 + k + 9]));
    }
    const float* W2p = W2 + (size_t)le * 2048;    // [32][64]
    for (int idx = t; idx < 512; idx += 256) {    // (kb 0..3, nt 0..3, ln)
        int kb = idx >> 7, nt = (idx >> 5) & 3, ln = idx & 31;
        int g = ln >> 2, tig = ln & 3;
        int n = nt * 8 + g, k = kb * 16 + 2 * tig;
        *(uint2*)(base + 32768 + idx * 8) = make_uint2(
            h2pk(W2p[n * 64 + k], W2p[n * 64 + k + 1]),
            h2pk(W2p[n * 64 + k + 8], W2p[n * 64 + k + 9]));
    }
    const float* W3p = W3 + (size_t)le * 8192;    // [256][32]
    for (int idx = t; idx < 2048; idx += 256) {   // (kb 0..1, nt 0..31, ln)
        int kb = idx >> 10, nt = (idx >> 5) & 31, ln = idx & 31;
        int g = ln >> 2, tig = ln & 3;
        int n = nt * 8 + g, k = kb * 16 + 2 * tig;
        *(uint2*)(base + 36864 + idx * 8) = make_uint2(
            h2pk(W3p[n * 32 + k], W3p[n * 32 + k + 1]),
            h2pk(W3p[n * 32 + k + 8], W3p[n * 32 + k + 9]));
    }
    if ((le & 7) == 0) {
        int l = le >> 3;
        const float* b3p = b3 + (size_t)l * 2048;  // [8][256]
        unsigned char* bb = g_w + B3OFF + (size_t)l * 4096;
        for (int idx = t; idx < 1024; idx += 256) {  // (nt 0..31, ln)
            int nt = idx >> 5, ln = idx & 31;
            int g = ln >> 2, tig = ln & 3;
            int n = nt * 8 + g;
            *(uint32_t*)(bb + idx * 4) = h2pk(b3p[2 * tig * 256 + n], b3p[(2 * tig + 1) * 256 + n]);
        }
    }
}

// ---------------- smem layout (bytes), TM=64, 2 CTAs/SM ----------------
#define XFRAG 0          // 65536: X A-frags uint4 [(kb*4+rt)*512 + ln*16], lo @ +32768
#define XLO   32768
#define H1F   65536      // 8192 : h1 A-frags [(kb*4+rt)*512 + ln*16], kb 0..3
#define H2F   73728      // 4096 : h2 A-frags [(kb*4+rt)*512 + ln*16], kb 0..1
#define WSOFT 77824      // 2048 (64 x 8 f32)
#define B1D   79872      // 512 : double-buffered b1 [2][64]
#define B2D   80384      // 256 : double-buffered b2 [2][32]
#define SMEM_BYTES 80640

__global__ void __launch_bounds__(NTH, 2)
moe_mma_kernel(const float* __restrict__ src,
               const float* __restrict__ b1, const float* __restrict__ b2,
               const float* __restrict__ masks, float* __restrict__ out)
{
    extern __shared__ char smem[];
    const int tid = threadIdx.x;
    const int w = tid >> 5;
    const int ln = tid & 31;
    const int g = ln >> 2;
    const int tig = ln & 3;
    const int rt1 = w & 3;       // G1/G2 row tile (0..3)
    const int nh1 = w >> 2;      // G1/G2 n-half (0..1)
    const int rp  = w & 1;       // G3 rowtile-pair
    const int nq1 = w >> 1;      // G3 n-quarter 0..3
    const int rowbase = blockIdx.x * TM;

    float* wsoft = (float*)(smem + WSOFT);
    float* b1d = (float*)(smem + B1D);   // [2][64]
    float* b2d = (float*)(smem + B2D);   // [2][32]

    // initial X -> fp16 hi/lo A-fragment image (4 threads per row); X stays exact
    {
        const int r = tid >> 2;
        const int q4 = tid & 3;
        const float* sp = src + (size_t)(rowbase + r) * ND;
        const int rt = r >> 4;
        const int rsel = ((r & 15) >= 8) ? 1 : 0;
        #pragma unroll 4
        for (int c = 64 * q4; c < 64 * q4 + 64; c += 2) {
            int kb = c >> 4, kk = c & 15;
            int tigw = (kk & 7) >> 1;
            int reg = rsel + ((kk >= 8) ? 2 : 0);
            uint32_t hi, lo;
            split2(sp[c], sp[c + 1], hi, lo);
            uint32_t off = (uint32_t)((kb * 4 + rt) * 512 + (4 * (r & 7) + tigw) * 16 + reg * 4);
            *(uint32_t*)(smem + XFRAG + off) = hi;
            *(uint32_t*)(smem + XFRAG + XLO + off) = lo;
        }
    }

    float xacc[2][8][4];

    for (int l = 0; l < NL; l++) {
        // ---- layer top: softmax weights, expert-0 biases ----
        if (tid < TM) {
            const int r = tid;
            const float* mp = masks + ((size_t)l * NB + rowbase + r) * NE;
            float m[8], mx = -1e30f;
            #pragma unroll
            for (int e = 0; e < 8; e++) { m[e] = mp[e]; mx = fmaxf(mx, m[e]); }
            float s = 0.f;
            #pragma unroll
            for (int e = 0; e < 8; e++) { m[e] = expf(m[e] - mx); s += m[e]; }
            s = 1.f / s;
            #pragma unroll
            for (int e = 0; e < 8; e++) wsoft[r * 8 + e] = m[e] * s;
        }
        if (tid < 64) b1d[tid] = b1[(size_t)(l * 8) * 64 + tid];
        else if (tid < 96) b2d[tid - 64] = b2[(size_t)(l * 8) * 32 + tid - 64];
        #pragma unroll
        for (int i = 0; i < 2; i++)
            #pragma unroll
            for (int j = 0; j < 8; j++)
                #pragma unroll
                for (int q = 0; q < 4; q++) xacc[i][j][q] = 0.f;
        __syncthreads();   // wsoft, e0 biases, xfrag (prev layer) visible

        for (int e = 0; e < NE; e++) {
            const int idx = l * 8 + e;
            const unsigned char* wpe = g_w + (size_t)idx * PER_LE;

            // ---- G1: X (smem) x W1 (direct LDG), hi/lo split accumulators ----
            float c1h[4][4], c1l[4][4];
            #pragma unroll
            for (int j = 0; j < 4; j++)
                #pragma unroll
                for (int q = 0; q < 4; q++) { c1h[j][q] = 0.f; c1l[j][q] = 0.f; }
            {
                const uint2* w1g = (const uint2*)wpe;
                #pragma unroll
                for (int kb = 0; kb < 16; kb++) {
                    const char* xb = smem + XFRAG + (kb * 4 + rt1) * 512 + ln * 16;
                    uint4 Ah = *(const uint4*)xb;
                    uint4 Al = *(const uint4*)(xb + XLO);
                    #pragma unroll
                    for (int ntl = 0; ntl < 4; ntl++) {
                        uint2 b = w1g[(kb * 8 + nh1 * 4 + ntl) * 32 + ln];
                        MMA16(c1h[ntl], Ah, b.x, b.y);
                        MMA16(c1l[ntl], Al, b.x, b.y);
                    }
                }
            }

            // ---- D1 epilogue: combine + bias + relu -> h1 A-frags ----
            {
                const float* b1c = b1d + (e & 1) * 64;
                float v[4][4];
                #pragma unroll
                for (int ntl = 0; ntl < 4; ntl++)
                    #pragma unroll
                    for (int ci = 0; ci < 4; ci++) {
                        int h = (nh1 * 4 + ntl) * 8 + 2 * tig + (ci & 1);
                        v[ntl][ci] = fmaxf(c1h[ntl][ci] + c1l[ntl][ci] + b1c[h], 0.f);
                    }
                #pragma unroll
                for (int kbl = 0; kbl < 2; kbl++) {
                    uint4 HI;
                    HI.x = h2pk(v[2 * kbl][0], v[2 * kbl][1]);
                    HI.y = h2pk(v[2 * kbl][2], v[2 * kbl][3]);
                    HI.z = h2pk(v[2 * kbl + 1][0], v[2 * kbl + 1][1]);
                    HI.w = h2pk(v[2 * kbl + 1][2], v[2 * kbl + 1][3]);
                    *(uint4*)(smem + H1F + ((nh1 * 2 + kbl) * 4 + rt1) * 512 + ln * 16) = HI;
                }
            }
            __syncthreads();   // B1: h1 visible (also: prev G3's H2F readers done)

            // prefetch next expert's biases into the other slot
            if (e < 7) {
                if (tid < 64) b1d[((e + 1) & 1) * 64 + tid] = b1[(size_t)(idx + 1) * 64 + tid];
                else if (tid < 96) b2d[((e + 1) & 1) * 32 + tid - 64] = b2[(size_t)(idx + 1) * 32 + tid - 64];
            }

            // ---- G2: h1 (smem) x W2 (direct LDG), even/odd-kb split accumulators ----
            float c2a[2][4], c2b[2][4];
            #pragma unroll
            for (int j = 0; j < 2; j++)
                #pragma unroll
                for (int q = 0; q < 4; q++) { c2a[j][q] = 0.f; c2b[j][q] = 0.f; }
            {
                const uint2* w2g = (const uint2*)(wpe + 32768);
                #pragma unroll
                for (int kb = 0; kb < 4; kb++) {
                    uint4 Ah = *(const uint4*)(smem + H1F + (kb * 4 + rt1) * 512 + ln * 16);
                    #pragma unroll
                    for (int nt = 0; nt < 2; nt++) {
                        uint2 b = w2g[(kb * 4 + 2 * nh1 + nt) * 32 + ln];
                        if (kb & 1) { MMA16(c2b[nt], Ah, b.x, b.y); }
                        else        { MMA16(c2a[nt], Ah, b.x, b.y); }
                    }
                }
            }
            // ---- D2 epilogue: combine + bias + relu, *softmax -> h2 A-frags ----
            {
                const float* b2c = b2d + (e & 1) * 32;
                float wg0 = wsoft[(16 * rt1 + g) * 8 + e];
                float wg1 = wsoft[(16 * rt1 + 8 + g) * 8 + e];
                float v[2][4];
                #pragma unroll
                for (int nt = 0; nt < 2; nt++)
                    #pragma unroll
                    for (int ci = 0; ci < 4; ci++) {
                        int h = 16 * nh1 + 8 * nt + 2 * tig + (ci & 1);
                        v[nt][ci] = fmaxf(c2a[nt][ci] + c2b[nt][ci] + b2c[h], 0.f) * ((ci < 2) ? wg0 : wg1);
                    }
                uint4 HI;
                HI.x = h2pk(v[0][0], v[0][1]);
                HI.y = h2pk(v[0][2], v[0][3]);
                HI.z = h2pk(v[1][0], v[1][1]);
                HI.w = h2pk(v[1][2], v[1][3]);
                *(uint4*)(smem + H2F + (nh1 * 4 + rt1) * 512 + ln * 16) = HI;
            }
            __syncthreads();   // B2: h2 visible (also: h1 readers done)

            // ---- G3: h2 (smem) x W3 (direct LDG), warp = (2 rt, 8 nt) ----
            {
                const uint2* w3g = (const uint2*)(wpe + 36864);
                uint4 AH[2][2];
                #pragma unroll
                for (int rt = 0; rt < 2; rt++)
                    #pragma unroll
                    for (int kb = 0; kb < 2; kb++)
                        AH[rt][kb] = *(const uint4*)(smem + H2F + (kb * 4 + 2 * rp + rt) * 512 + ln * 16);
                #pragma unroll
                for (int kb = 0; kb < 2; kb++)
                    #pragma unroll
                    for (int nt = 0; nt < 8; nt++) {
                        uint2 b = w3g[(kb * 32 + 8 * nq1 + nt) * 32 + ln];
                        MMA16(xacc[0][nt], AH[0][kb], b.x, b.y);
                        MMA16(xacc[1][nt], AH[1][kb], b.x, b.y);
                    }
                if (e == 0) {   // weighted-b3 via K=8 fp16 MMA (experts as K)
                    const unsigned char* gb3 = g_w + B3OFF + (size_t)l * 4096;
                    #pragma unroll
                    for (int rt = 0; rt < 2; rt++) {
                        int r0 = 32 * rp + 16 * rt + g;
                        uint32_t a0 = h2pk(wsoft[r0 * 8 + 2 * tig], wsoft[r0 * 8 + 2 * tig + 1]);
                        uint32_t a1 = h2pk(wsoft[(r0 + 8) * 8 + 2 * tig], wsoft[(r0 + 8) * 8 + 2 * tig + 1]);
                        #pragma unroll
                        for (int nt = 0; nt < 8; nt++) {
                            uint32_t b = *(const uint32_t*)(gb3 + ((8 * nq1 + nt) * 32 + ln) * 4);
                            MMA8(xacc[rt][nt], a0, a1, b);
                        }
                    }
                }
            }
            // no barrier: G1(e+1) reads only XFRAG/W1; H2F rewrite fenced by B1(e+1).
        } // experts

        // ---- layer end: xacc -> XFRAG (exact hi/lo) or out ----
        if (l == NL - 1) {
            #pragma unroll
            for (int rt = 0; rt < 2; rt++) {
                int r0 = 32 * rp + rt * 16 + g;
                #pragma unroll
                for (int nt = 0; nt < 8; nt++) {
                    int col = 64 * nq1 + nt * 8 + tig * 2;
                    float* cc = xacc[rt][nt];
                    *(float2*)(out + (size_t)(rowbase + r0) * ND + col) = make_float2(cc[0], cc[1]);
                    *(float2*)(out + (size_t)(rowbase + r0 + 8) * ND + col) = make_float2(cc[2], cc[3]);
                }
            }
        } else {
            #pragma unroll
            for (int rt = 0; rt < 2; rt++) {
                #pragma unroll
                for (int kbl = 0; kbl < 4; kbl++) {
                    float* ce = xacc[rt][2 * kbl];
                    float* co = xacc[rt][2 * kbl + 1];
                    uint4 HI, LO;
                    split2(ce[0], ce[1], HI.x, LO.x);
                    split2(ce[2], ce[3], HI.y, LO.y);
                    split2(co[0], co[1], HI.z, LO.z);
                    split2(co[2], co[3], HI.w, LO.w);
                    uint32_t off = (uint32_t)(((4 * nq1 + kbl) * 4 + 2 * rp + rt) * 512 + ln * 16);
                    *(uint4*)(smem + XFRAG + off) = HI;
                    *(uint4*)(smem + XFRAG + XLO + off) = LO;
                }
            }
        }
        // next layer-top __syncthreads() fences xfrag writes vs G1 reads
    } // layers
}

extern "C" void kernel_launch(void* const* d_in, const int* in_sizes, int n_in,
                              void* d_out, int out_size)
{
    const float* src   = (const float*)d_in[0];
    const float* W1    = (const float*)d_in[1];
    const float* b1    = (const float*)d_in[2];
    const float* W2    = (const float*)d_in[3];
    const float* b2    = (const float*)d_in[4];
    const float* W3    = (const float*)d_in[5];
    const float* b3    = (const float*)d_in[6];
    const float* masks = (const float*)d_in[7];
    float* out = (float*)d_out;
    (void)in_sizes; (void)n_in; (void)out_size;

    prep_kernel<<<64, 256>>>(W1, W2, W3, b3);
    cudaFuncSetAttribute(moe_mma_kernel,
                         cudaFuncAttributeMaxDynamicSharedMemorySize, SMEM_BYTES);
    moe_mma_kernel<<<NB / TM, NTH, SMEM_BYTES>>>(src, b1, b2, masks, out);
}

// round 16
// speedup vs baseline: 1.1638x; 1.1638x over previous
#include <cuda_runtime.h>
#include <cuda_fp16.h>
#include <cstdint>
#include <math.h>

#define NL 8
#define NE 8
#define ND 256
#define NB 16384
#define TM 64
#define NTH 256

// ---------------- helpers ----------------
__device__ __forceinline__ uint32_t h2pk(float a, float b) {
    __half2 h = __floats2half2_rn(a, b);
    return *(uint32_t*)&h;
}
// exact split: a = hi + lo (both fp16), packed pairwise
__device__ __forceinline__ void split2(float a, float b, uint32_t& hi, uint32_t& lo) {
    __half ha = __float2half_rn(a), hb = __float2half_rn(b);
    __half2 hh = __halves2half2(ha, hb);
    hi = *(uint32_t*)&hh;
    lo = h2pk(a - __half2float(ha), b - __half2float(hb));
}

#define MMA16(c, A, b0, b1) \
    asm volatile("mma.sync.aligned.m16n8k16.row.col.f32.f16.f16.f32 " \
        "{%0,%1,%2,%3},{%4,%5,%6,%7},{%8,%9},{%0,%1,%2,%3};" \
        : "+f"((c)[0]), "+f"((c)[1]), "+f"((c)[2]), "+f"((c)[3]) \
        : "r"((A).x), "r"((A).y), "r"((A).z), "r"((A).w), "r"(b0), "r"(b1))

#define MMA8(c, a0, a1, b0) \
    asm volatile("mma.sync.aligned.m16n8k8.row.col.f32.f16.f16.f32 " \
        "{%0,%1,%2,%3},{%4,%5},{%6},{%0,%1,%2,%3};" \
        : "+f"((c)[0]), "+f"((c)[1]), "+f"((c)[2]), "+f"((c)[3]) \
        : "r"(a0), "r"(a1), "r"(b0))

// ---------------- global weight images (fp16 B-fragments) ----------------
// per (l,e): W1 32768 (kb-major contiguous) | W2 4096 | W3 16384
#define PER_LE 53248
#define B3OFF (64 * PER_LE)
__device__ __align__(16) unsigned char g_w[B3OFF + 8 * 4096];

__global__ void prep_kernel(const float* __restrict__ W1, const float* __restrict__ W2,
                            const float* __restrict__ W3, const float* __restrict__ b3) {
    const int le = blockIdx.x;
    const int t = threadIdx.x;
    unsigned char* base = g_w + (size_t)le * PER_LE;

    const float* W1p = W1 + (size_t)le * 16384;   // [64][256]
    for (int idx = t; idx < 4096; idx += 256) {   // (kb 0..15, nt 0..7, ln)
        int kb = idx >> 8, nt = (idx >> 5) & 7, ln = idx & 31;
        int g = ln >> 2, tig = ln & 3;
        int n = nt * 8 + g, k = kb * 16 + 2 * tig;
        *(uint2*)(base + idx * 8) = make_uint2(
            h2pk(W1p[n * 256 + k], W1p[n * 256 + k + 1]),
            h2pk(W1p[n * 256 + k + 8], W1p[n * 256 + k + 9]));
    }
    const float* W2p = W2 + (size_t)le * 2048;    // [32][64]
    for (int idx = t; idx < 512; idx += 256) {    // (kb 0..3, nt 0..3, ln)
        int kb = idx >> 7, nt = (idx >> 5) & 3, ln = idx & 31;
        int g = ln >> 2, tig = ln & 3;
        int n = nt * 8 + g, k = kb * 16 + 2 * tig;
        *(uint2*)(base + 32768 + idx * 8) = make_uint2(
            h2pk(W2p[n * 64 + k], W2p[n * 64 + k + 1]),
            h2pk(W2p[n * 64 + k + 8], W2p[n * 64 + k + 9]));
    }
    const float* W3p = W3 + (size_t)le * 8192;    // [256][32]
    for (int idx = t; idx < 2048; idx += 256) {   // (kb 0..1, nt 0..31, ln)
        int kb = idx >> 10, nt = (idx >> 5) & 31, ln = idx & 31;
        int g = ln >> 2, tig = ln & 3;
        int n = nt * 8 + g, k = kb * 16 + 2 * tig;
        *(uint2*)(base + 36864 + idx * 8) = make_uint2(
            h2pk(W3p[n * 32 + k], W3p[n * 32 + k + 1]),
            h2pk(W3p[n * 32 + k + 8], W3p[n * 32 + k + 9]));
    }
    if ((le & 7) == 0) {
        int l = le >> 3;
        const float* b3p = b3 + (size_t)l * 2048;  // [8][256]
        unsigned char* bb = g_w + B3OFF + (size_t)l * 4096;
        for (int idx = t; idx < 1024; idx += 256) {  // (nt 0..31, ln)
            int nt = idx >> 5, ln = idx & 31;
            int g = ln >> 2, tig = ln & 3;
            int n = nt * 8 + g;
            *(uint32_t*)(bb + idx * 4) = h2pk(b3p[2 * tig * 256 + n], b3p[(2 * tig + 1) * 256 + n]);
        }
    }
}

// ---------------- smem layout (bytes), TM=64, 2 CTAs/SM ----------------
#define XFRAG 0          // 65536: X A-frags uint4 [(kb*4+rt)*512 + ln*16], lo @ +32768
#define XLO   32768
#define H1F   65536      // 8192 : h1 A-frags [(kb*4+rt)*512 + ln*16], kb 0..3
#define H2F   73728      // 4096 : h2 A-frags [(kb*4+rt)*512 + ln*16], kb 0..1
#define WSOFT 77824      // 2048 (64 x 8 f32)
#define B1D   79872      // 512 : double-buffered b1 [2][64]
#define B2D   80384      // 256 : double-buffered b2 [2][32]
#define SMEM_BYTES 80640

__global__ void __launch_bounds__(NTH, 2)
moe_mma_kernel(const float* __restrict__ src,
               const float* __restrict__ b1, const float* __restrict__ b2,
               const float* __restrict__ masks, float* __restrict__ out)
{
    extern __shared__ char smem[];
    const int tid = threadIdx.x;
    const int w = tid >> 5;
    const int ln = tid & 31;
    const int g = ln >> 2;
    const int tig = ln & 3;
    const int rt1 = w & 3;       // G1/G2 row tile (0..3)
    const int nh1 = w >> 2;      // G1/G2 n-half (0..1)
    const int rp  = w & 1;       // G3 rowtile-pair
    const int nq1 = w >> 1;      // G3 n-quarter 0..3
    const int rowbase = blockIdx.x * TM;

    float* wsoft = (float*)(smem + WSOFT);
    float* b1d = (float*)(smem + B1D);   // [2][64]
    float* b2d = (float*)(smem + B2D);   // [2][32]

    // initial X -> fp16 hi/lo A-fragment image (4 threads per row); X stays exact
    {
        const int r = tid >> 2;
        const int q4 = tid & 3;
        const float* sp = src + (size_t)(rowbase + r) * ND;
        const int rt = r >> 4;
        const int rsel = ((r & 15) >= 8) ? 1 : 0;
        #pragma unroll 4
        for (int c = 64 * q4; c < 64 * q4 + 64; c += 2) {
            int kb = c >> 4, kk = c & 15;
            int tigw = (kk & 7) >> 1;
            int reg = rsel + ((kk >= 8) ? 2 : 0);
            uint32_t hi, lo;
            split2(sp[c], sp[c + 1], hi, lo);
            uint32_t off = (uint32_t)((kb * 4 + rt) * 512 + (4 * (r & 7) + tigw) * 16 + reg * 4);
            *(uint32_t*)(smem + XFRAG + off) = hi;
            *(uint32_t*)(smem + XFRAG + XLO + off) = lo;
        }
    }

    float xacc[2][8][4];

    for (int l = 0; l < NL; l++) {
        // ---- layer top: softmax weights, expert-0 biases ----
        if (tid < TM) {
            const int r = tid;
            const float* mp = masks + ((size_t)l * NB + rowbase + r) * NE;
            float m[8], mx = -1e30f;
            #pragma unroll
            for (int e = 0; e < 8; e++) { m[e] = mp[e]; mx = fmaxf(mx, m[e]); }
            float s = 0.f;
            #pragma unroll
            for (int e = 0; e < 8; e++) { m[e] = expf(m[e] - mx); s += m[e]; }
            s = 1.f / s;
            #pragma unroll
            for (int e = 0; e < 8; e++) wsoft[r * 8 + e] = m[e] * s;
        }
        if (tid < 64) b1d[tid] = b1[(size_t)(l * 8) * 64 + tid];
        else if (tid < 96) b2d[tid - 64] = b2[(size_t)(l * 8) * 32 + tid - 64];
        #pragma unroll
        for (int i = 0; i < 2; i++)
            #pragma unroll
            for (int j = 0; j < 8; j++)
                #pragma unroll
                for (int q = 0; q < 4; q++) xacc[i][j][q] = 0.f;
        __syncthreads();   // wsoft, e0 biases, xfrag (prev layer) visible

        for (int e = 0; e < NE; e++) {
            const int idx = l * 8 + e;
            const unsigned char* wpe = g_w + (size_t)idx * PER_LE;

            // ---- G1: X (smem) x W1 (direct LDG), warp = (1 rt, 4 nt) ----
            // nt processed in pairs: same-accumulator reuse distance 2 (was 1)
            float c1[4][4];
            #pragma unroll
            for (int j = 0; j < 4; j++)
                #pragma unroll
                for (int q = 0; q < 4; q++) c1[j][q] = 0.f;
            {
                const uint2* w1g = (const uint2*)wpe;
                #pragma unroll
                for (int kb = 0; kb < 16; kb++) {
                    const char* xb = smem + XFRAG + (kb * 4 + rt1) * 512 + ln * 16;
                    uint4 Ah = *(const uint4*)xb;
                    uint4 Al = *(const uint4*)(xb + XLO);
                    #pragma unroll
                    for (int np = 0; np < 2; np++) {
                        uint2 b0 = w1g[(kb * 8 + nh1 * 4 + 2 * np) * 32 + ln];
                        uint2 b1v = w1g[(kb * 8 + nh1 * 4 + 2 * np + 1) * 32 + ln];
                        MMA16(c1[2 * np], Ah, b0.x, b0.y);
                        MMA16(c1[2 * np + 1], Ah, b1v.x, b1v.y);
                        MMA16(c1[2 * np], Al, b0.x, b0.y);
                        MMA16(c1[2 * np + 1], Al, b1v.x, b1v.y);
                    }
                }
            }

            // ---- D1 epilogue: bias+relu -> h1 A-frags (register-local pack) ----
            {
                const float* b1c = b1d + (e & 1) * 64;
                float v[4][4];
                #pragma unroll
                for (int ntl = 0; ntl < 4; ntl++)
                    #pragma unroll
                    for (int ci = 0; ci < 4; ci++) {
                        int h = (nh1 * 4 + ntl) * 8 + 2 * tig + (ci & 1);
                        v[ntl][ci] = fmaxf(c1[ntl][ci] + b1c[h], 0.f);
                    }
                #pragma unroll
                for (int kbl = 0; kbl < 2; kbl++) {
                    uint4 HI;
                    HI.x = h2pk(v[2 * kbl][0], v[2 * kbl][1]);
                    HI.y = h2pk(v[2 * kbl][2], v[2 * kbl][3]);
                    HI.z = h2pk(v[2 * kbl + 1][0], v[2 * kbl + 1][1]);
                    HI.w = h2pk(v[2 * kbl + 1][2], v[2 * kbl + 1][3]);
                    *(uint4*)(smem + H1F + ((nh1 * 2 + kbl) * 4 + rt1) * 512 + ln * 16) = HI;
                }
            }
            __syncthreads();   // B1: h1 visible (also: prev G3's H2F readers done)

            // prefetch next expert's biases into the other slot
            if (e < 7) {
                if (tid < 64) b1d[((e + 1) & 1) * 64 + tid] = b1[(size_t)(idx + 1) * 64 + tid];
                else if (tid < 96) b2d[((e + 1) & 1) * 32 + tid - 64] = b2[(size_t)(idx + 1) * 32 + tid - 64];
            }

            // ---- G2: h1 (smem) x W2 (direct LDG), warp = (1 rt, 2 nt) ----
            float c2[2][4];
            #pragma unroll
            for (int j = 0; j < 2; j++)
                #pragma unroll
                for (int q = 0; q < 4; q++) c2[j][q] = 0.f;
            {
                const uint2* w2g = (const uint2*)(wpe + 32768);
                #pragma unroll
                for (int kb = 0; kb < 4; kb++) {
                    uint4 Ah = *(const uint4*)(smem + H1F + (kb * 4 + rt1) * 512 + ln * 16);
                    #pragma unroll
                    for (int nt = 0; nt < 2; nt++) {
                        uint2 b = w2g[(kb * 4 + 2 * nh1 + nt) * 32 + ln];
                        MMA16(c2[nt], Ah, b.x, b.y);
                    }
                }
            }
            // ---- D2 epilogue: bias+relu, *softmax -> h2 A-frags ----
            {
                const float* b2c = b2d + (e & 1) * 32;
                float wg0 = wsoft[(16 * rt1 + g) * 8 + e];
                float wg1 = wsoft[(16 * rt1 + 8 + g) * 8 + e];
                float v[2][4];
                #pragma unroll
                for (int nt = 0; nt < 2; nt++)
                    #pragma unroll
                    for (int ci = 0; ci < 4; ci++) {
                        int h = 16 * nh1 + 8 * nt + 2 * tig + (ci & 1);
                        v[nt][ci] = fmaxf(c2[nt][ci] + b2c[h], 0.f) * ((ci < 2) ? wg0 : wg1);
                    }
                uint4 HI;
                HI.x = h2pk(v[0][0], v[0][1]);
                HI.y = h2pk(v[0][2], v[0][3]);
                HI.z = h2pk(v[1][0], v[1][1]);
                HI.w = h2pk(v[1][2], v[1][3]);
                *(uint4*)(smem + H2F + (nh1 * 4 + rt1) * 512 + ln * 16) = HI;
            }
            __syncthreads();   // B2: h2 visible (also: h1 readers done)

            // ---- G3: h2 (smem) x W3 (direct LDG), warp = (2 rt, 8 nt) ----
            {
                const uint2* w3g = (const uint2*)(wpe + 36864);
                uint4 AH[2][2];
                #pragma unroll
                for (int rt = 0; rt < 2; rt++)
                    #pragma unroll
                    for (int kb = 0; kb < 2; kb++)
                        AH[rt][kb] = *(const uint4*)(smem + H2F + (kb * 4 + 2 * rp + rt) * 512 + ln * 16);
                #pragma unroll
                for (int kb = 0; kb < 2; kb++)
                    #pragma unroll
                    for (int nt = 0; nt < 8; nt++) {
                        uint2 b = w3g[(kb * 32 + 8 * nq1 + nt) * 32 + ln];
                        MMA16(xacc[0][nt], AH[0][kb], b.x, b.y);
                        MMA16(xacc[1][nt], AH[1][kb], b.x, b.y);
                    }
                if (e == 0) {   // weighted-b3 via K=8 fp16 MMA (experts as K)
                    const unsigned char* gb3 = g_w + B3OFF + (size_t)l * 4096;
                    #pragma unroll
                    for (int rt = 0; rt < 2; rt++) {
                        int r0 = 32 * rp + 16 * rt + g;
                        uint32_t a0 = h2pk(wsoft[r0 * 8 + 2 * tig], wsoft[r0 * 8 + 2 * tig + 1]);
                        uint32_t a1 = h2pk(wsoft[(r0 + 8) * 8 + 2 * tig], wsoft[(r0 + 8) * 8 + 2 * tig + 1]);
                        #pragma unroll
                        for (int nt = 0; nt < 8; nt++) {
                            uint32_t b = *(const uint32_t*)(gb3 + ((8 * nq1 + nt) * 32 + ln) * 4);
                            MMA8(xacc[rt][nt], a0, a1, b);
                        }
                    }
                }
            }
            // no barrier: G1(e+1) reads only XFRAG/W1; H2F rewrite fenced by B1(e+1).
        } // experts

        // ---- layer end: xacc -> XFRAG (exact hi/lo) or out ----
        if (l == NL - 1) {
            #pragma unroll
            for (int rt = 0; rt < 2; rt++) {
                int r0 = 32 * rp + rt * 16 + g;
                #pragma unroll
                for (int nt = 0; nt < 8; nt++) {
                    int col = 64 * nq1 + nt * 8 + tig * 2;
                    float* cc = xacc[rt][nt];
                    *(float2*)(out + (size_t)(rowbase + r0) * ND + col) = make_float2(cc[0], cc[1]);
                    *(float2*)(out + (size_t)(rowbase + r0 + 8) * ND + col) = make_float2(cc[2], cc[3]);
                }
            }
        } else {
            #pragma unroll
            for (int rt = 0; rt < 2; rt++) {
                #pragma unroll
                for (int kbl = 0; kbl < 4; kbl++) {
                    float* ce = xacc[rt][2 * kbl];
                    float* co = xacc[rt][2 * kbl + 1];
                    uint4 HI, LO;
                    split2(ce[0], ce[1], HI.x, LO.x);
                    split2(ce[2], ce[3], HI.y, LO.y);
                    split2(co[0], co[1], HI.z, LO.z);
                    split2(co[2], co[3], HI.w, LO.w);
                    uint32_t off = (uint32_t)(((4 * nq1 + kbl) * 4 + 2 * rp + rt) * 512 + ln * 16);
                    *(uint4*)(smem + XFRAG + off) = HI;
                    *(uint4*)(smem + XFRAG + XLO + off) = LO;
                }
            }
        }
        // next layer-top __syncthreads() fences xfrag writes vs G1 reads
    } // layers
}

extern "C" void kernel_launch(void* const* d_in, const int* in_sizes, int n_in,
                              void* d_out, int out_size)
{
    const float* src   = (const float*)d_in[0];
    const float* W1    = (const float*)d_in[1];
    const float* b1    = (const float*)d_in[2];
    const float* W2    = (const float*)d_in[3];
    const float* b2    = (const float*)d_in[4];
    const float* W3    = (const float*)d_in[5];
    const float* b3    = (const float*)d_in[6];
    const float* masks = (const float*)d_in[7];
    float* out = (float*)d_out;
    (void)in_sizes; (void)n_in; (void)out_size;

    prep_kernel<<<64, 256>>>(W1, W2, W3, b3);
    cudaFuncSetAttribute(moe_mma_kernel,
                         cudaFuncAttributeMaxDynamicSharedMemorySize, SMEM_BYTES);
    moe_mma_kernel<<<NB / TM, NTH, SMEM_BYTES>>>(src, b1, b2, masks, out);
}